// round 16
// baseline (speedup 1.0000x reference)
#include <cuda_runtime.h>
#include <cuda_bf16.h>

#define NN   20000
#define EE   200000
#define IND  500
#define HD   256
#define OD   16
#define MHD  64

// -------- scratch (alloc-free rule: __device__ globals) --------
__device__ float g_t1[NN * 64];        // MLP hidden
__device__ float g_h [NN * HD];        // h, then xb (mutated in place)
__device__ float g_H [NN * HD];        // sheaf-transformed H per layer
__device__ float g_LH[NN * HD];        // scatter accumulator
__device__ float g_pq[NN * 128];       // [n][0:64]=p=h@Wa^T, [64:128]=q=h@Wb^T
__device__ float g_Fs[EE * 16];
__device__ float g_Ft[EE * 16];
__device__ float g_Wpq[128 * HD];      // rows 0-63 = Wa, rows 64-127 = Wb
__device__ float g_Wd2T[2 * 64 * 64];  // Wd2[l] transposed -> [f][g]
__device__ float g_zero[128];          // zero bias (BSS zero-init, never written)

// -------- weight prep --------
__global__ void prep_kernel(const float* __restrict__ Wm1,
                            const float* __restrict__ Wd2) {
    int i = blockIdx.x * blockDim.x + threadIdx.x;
    if (i < 128 * 256) {
        int r = i >> 8, k = i & 255;
        g_Wpq[i] = (r < 64) ? Wm1[r * 512 + k] : Wm1[(r - 64) * 512 + 256 + k];
    }
    if (i < 2 * 64 * 64) {
        int l = i / 4096, rr = i % 4096;
        int f = rr / 64, g = rr % 64;
        g_Wd2T[i] = Wd2[l * 4096 + g * 64 + f];
    }
}

// -------- C = act(A @ W^T + b), A[M,Kd], W[Nc,Kd] --------
// 128x64 tile, 256 threads, 8x4 per thread, reg-staged prefetch.
__global__ void sgemm_bias(const float* __restrict__ A,
                           const float* __restrict__ W,
                           const float* __restrict__ bias,
                           float* __restrict__ C,
                           int M, int Kd, int Nc, int doRelu) {
    __shared__ float As[16][132];
    __shared__ float Bs[16][68];
    int t  = threadIdx.x;
    int tx = t & 15, ty = t >> 4;           // tx: 16 col groups, ty: 16 row groups
    int m0 = blockIdx.y * 128, n0 = blockIdx.x * 64;
    float acc[8][4];
#pragma unroll
    for (int i = 0; i < 8; i++)
#pragma unroll
        for (int j = 0; j < 4; j++) acc[i][j] = 0.f;

    float pa[8], pb[4];
    // prefetch k0 = 0
#pragma unroll
    for (int i = 0; i < 8; i++) {
        int q = t + i * 256; int kk = q & 15, mm = q >> 4;
        int m = m0 + mm;
        pa[i] = (m < M && kk < Kd) ? A[(size_t)m * Kd + kk] : 0.f;
    }
#pragma unroll
    for (int i = 0; i < 4; i++) {
        int q = t + i * 256; int kk = q & 15, nn = q >> 4;
        int n = n0 + nn;
        pb[i] = (n < Nc && kk < Kd) ? W[(size_t)n * Kd + kk] : 0.f;
    }

    for (int k0 = 0; k0 < Kd; k0 += 16) {
        // commit staged tile
#pragma unroll
        for (int i = 0; i < 8; i++) {
            int q = t + i * 256; As[q & 15][q >> 4] = pa[i];
        }
#pragma unroll
        for (int i = 0; i < 4; i++) {
            int q = t + i * 256; Bs[q & 15][q >> 4] = pb[i];
        }
        __syncthreads();
        // prefetch next tile while computing this one
        int k1 = k0 + 16;
        if (k1 < Kd) {
#pragma unroll
            for (int i = 0; i < 8; i++) {
                int q = t + i * 256; int kk = q & 15, mm = q >> 4;
                int m = m0 + mm, k = k1 + kk;
                pa[i] = (m < M && k < Kd) ? A[(size_t)m * Kd + k] : 0.f;
            }
#pragma unroll
            for (int i = 0; i < 4; i++) {
                int q = t + i * 256; int kk = q & 15, nn = q >> 4;
                int n = n0 + nn, k = k1 + kk;
                pb[i] = (n < Nc && k < Kd) ? W[(size_t)n * Kd + k] : 0.f;
            }
        }
#pragma unroll
        for (int kk = 0; kk < 16; kk++) {
            float4 a0 = *(const float4*)&As[kk][ty * 8];
            float4 a1 = *(const float4*)&As[kk][ty * 8 + 4];
            float4 b4 = *(const float4*)&Bs[kk][tx * 4];
            float a[8] = {a0.x, a0.y, a0.z, a0.w, a1.x, a1.y, a1.z, a1.w};
            float b[4] = {b4.x, b4.y, b4.z, b4.w};
#pragma unroll
            for (int i = 0; i < 8; i++)
#pragma unroll
                for (int j = 0; j < 4; j++) acc[i][j] += a[i] * b[j];
        }
        __syncthreads();
    }
#pragma unroll
    for (int i = 0; i < 8; i++) {
        int m = m0 + ty * 8 + i;
        if (m >= M) continue;
#pragma unroll
        for (int j = 0; j < 4; j++) {
            int n = n0 + tx * 4 + j;
            if (n >= Nc) continue;
            float v = acc[i][j] + bias[n];
            if (doRelu) v = fmaxf(v, 0.f);
            C[(size_t)m * Nc + n] = v;
        }
    }
}

// -------- fused edge messages: gather pq, relu-add, project with Wm2 --------
__global__ void edge_fused_kernel(const int* __restrict__ ei,
                                  const float* __restrict__ bm1,
                                  const float* __restrict__ Wm2,
                                  const float* __restrict__ bm2) {
    __shared__ float sm[16][68];
    __shared__ float sW[16][65];
    int t  = threadIdx.x;
    int eb = blockIdx.x * 8;

#pragma unroll
    for (int q = t; q < 16 * 64; q += 256) {
        sW[q >> 6][q & 63] = Wm2[q];
    }
    {
        int msg = t >> 4, v = t & 15;
        int edge = eb + (msg >> 1);
        int second = msg & 1;
        int s = ei[edge], d = ei[EE + edge];
        int na = second ? d : s;
        int nb = second ? s : d;
        const float4* pq4 = (const float4*)g_pq;
        float4 pa = pq4[(size_t)na * 32 + v];
        float4 qb = pq4[(size_t)nb * 32 + 16 + v];
        float4 bb = ((const float4*)bm1)[v];
        sm[msg][v * 4 + 0] = fmaxf(pa.x + qb.x + bb.x, 0.f);
        sm[msg][v * 4 + 1] = fmaxf(pa.y + qb.y + bb.y, 0.f);
        sm[msg][v * 4 + 2] = fmaxf(pa.z + qb.z + bb.z, 0.f);
        sm[msg][v * 4 + 3] = fmaxf(pa.w + qb.w + bb.w, 0.f);
    }
    __syncthreads();
    {
        int msg = t >> 4, o = t & 15;
        float acc = bm2[o];
#pragma unroll
        for (int jj = 0; jj < 64; jj++)
            acc += sW[o][jj] * sm[msg][jj];
        int edge = eb + (msg >> 1);
        if (msg & 1) g_Ft[edge * 16 + o] = acc;
        else         g_Fs[edge * 16 + o] = acc;
    }
}

// -------- per-node sheaf transform (optionally fusing xb -= relu(LH)) --------
__global__ void sheaf_H_kernel(const float* __restrict__ Wd1, int l, int applyUpd) {
    __shared__ float xbs[4][256];
    __shared__ float tmps[4][256];
    int t  = threadIdx.x;
    int nb = blockIdx.x * 4;
    int n_loc = t >> 6, f = t & 63;
    {
        float4* x4g = (float4*)g_h;
        size_t idx = (size_t)(nb + n_loc) * 64 + f;
        float4 xv = x4g[idx];
        if (applyUpd) {
            float4 lv = ((const float4*)g_LH)[idx];
            xv.x -= fmaxf(lv.x, 0.f);
            xv.y -= fmaxf(lv.y, 0.f);
            xv.z -= fmaxf(lv.z, 0.f);
            xv.w -= fmaxf(lv.w, 0.f);
            x4g[idx] = xv;
        }
        ((float4*)xbs)[n_loc * 64 + f] = xv;
    }
    __syncthreads();
#pragma unroll
    for (int i = 0; i < 4; i++) {
        float acc = 0.f;
#pragma unroll
        for (int j = 0; j < 4; j++)
            acc += Wd1[l * 16 + j * 4 + i] * xbs[n_loc][j * 64 + f];
        tmps[n_loc][i * 64 + f] = acc;
    }
    __syncthreads();
    int node = nb + n_loc;
    float a0 = 0.f, a1 = 0.f, a2 = 0.f, a3 = 0.f;
#pragma unroll 8
    for (int ff = 0; ff < 64; ff++) {
        float wv = g_Wd2T[l * 4096 + ff * 64 + f];
        a0 += tmps[n_loc][ff] * wv;
        a1 += tmps[n_loc][64 + ff] * wv;
        a2 += tmps[n_loc][128 + ff] * wv;
        a3 += tmps[n_loc][192 + ff] * wv;
    }
    size_t base = (size_t)node * 256;
    g_H[base + f]       = a0;
    g_H[base + 64 + f]  = a1;
    g_H[base + 128 + f] = a2;
    g_H[base + 192 + f] = a3;
    g_LH[base + f] = 0.f; g_LH[base + 64 + f] = 0.f;
    g_LH[base + 128 + f] = 0.f; g_LH[base + 192 + f] = 0.f;
}

// -------- per-edge Bx + scatter into LH (register Bx, direct L2 gathers) --------
// 4 edges/block, 64 threads/edge: thread owns one float4 (j = quad>>4).
__global__ void edge_scatter_kernel(const int* __restrict__ ei) {
    __shared__ float sF[4][32];    // [edge][0:16]=Fs, [16:32]=Ft
    int t  = threadIdx.x;
    int e0 = blockIdx.x * 4;
    if (t < 128) {
        int e_loc = t >> 5, r = t & 31;
        int edge = e0 + e_loc;
        sF[e_loc][r] = (r < 16) ? g_Fs[edge * 16 + r] : g_Ft[edge * 16 + (r - 16)];
    }
    __syncthreads();
    int e_loc = t >> 6, q = t & 63;
    int j = q >> 4, fo = q & 15;           // this thread's output row j, float4 col fo
    int edge = e0 + e_loc;
    int s = ei[edge], d = ei[EE + edge];
    const float4* H4 = (const float4*)g_H;
    float4 hs[4], hd[4];
#pragma unroll
    for (int jj = 0; jj < 4; jj++) {
        hs[jj] = H4[(size_t)s * 64 + jj * 16 + fo];
        hd[jj] = H4[(size_t)d * 64 + jj * 16 + fo];
    }
    float4 bx[4];
#pragma unroll
    for (int i = 0; i < 4; i++) {
        float4 a = {0.f, 0.f, 0.f, 0.f};
#pragma unroll
        for (int jj = 0; jj < 4; jj++) {
            float ft = sF[e_loc][16 + i * 4 + jj];
            float fs = sF[e_loc][i * 4 + jj];
            a.x += ft * hd[jj].x - fs * hs[jj].x;
            a.y += ft * hd[jj].y - fs * hs[jj].y;
            a.z += ft * hd[jj].z - fs * hs[jj].z;
            a.w += ft * hd[jj].w - fs * hs[jj].w;
        }
        bx[i] = a;
    }
    float4 cs = {0.f, 0.f, 0.f, 0.f}, ct = {0.f, 0.f, 0.f, 0.f};
#pragma unroll
    for (int i = 0; i < 4; i++) {
        float fs = sF[e_loc][i * 4 + j];
        float ft = sF[e_loc][16 + i * 4 + j];
        cs.x += fs * bx[i].x; cs.y += fs * bx[i].y; cs.z += fs * bx[i].z; cs.w += fs * bx[i].w;
        ct.x += ft * bx[i].x; ct.y += ft * bx[i].y; ct.z += ft * bx[i].z; ct.w += ft * bx[i].w;
    }
    float* ps = &g_LH[(size_t)s * 256 + j * 64 + fo * 4];
    float* pd = &g_LH[(size_t)d * 256 + j * 64 + fo * 4];
    asm volatile("red.global.add.v4.f32 [%0], {%1, %2, %3, %4};"
                 :: "l"(ps), "f"(-cs.x), "f"(-cs.y), "f"(-cs.z), "f"(-cs.w) : "memory");
    asm volatile("red.global.add.v4.f32 [%0], {%1, %2, %3, %4};"
                 :: "l"(pd), "f"(ct.x), "f"(ct.y), "f"(ct.z), "f"(ct.w) : "memory");
}

// -------- xb = xb - relu(LH) (final only) --------
__global__ void xb_update_kernel() {
    int i = blockIdx.x * blockDim.x + threadIdx.x;
    if (i < NN * 64) {
        float4 xv = ((float4*)g_h)[i];
        float4 lv = ((float4*)g_LH)[i];
        xv.x -= fmaxf(lv.x, 0.f);
        xv.y -= fmaxf(lv.y, 0.f);
        xv.z -= fmaxf(lv.z, 0.f);
        xv.w -= fmaxf(lv.w, 0.f);
        ((float4*)g_h)[i] = xv;
    }
}

extern "C" void kernel_launch(void* const* d_in, const int* in_sizes, int n_in,
                              void* d_out, int out_size) {
    const float* x    = (const float*)d_in[0];
    const int*   ei   = (const int*)  d_in[1];
    const float* Win1 = (const float*)d_in[2];
    const float* bin1 = (const float*)d_in[3];
    const float* Win2 = (const float*)d_in[4];
    const float* bin2 = (const float*)d_in[5];
    const float* Wm1  = (const float*)d_in[6];
    const float* bm1  = (const float*)d_in[7];
    const float* Wm2  = (const float*)d_in[8];
    const float* bm2  = (const float*)d_in[9];
    const float* Wd1  = (const float*)d_in[10];
    const float* Wd2  = (const float*)d_in[11];
    const float* Wo1  = (const float*)d_in[12];
    const float* bo1  = (const float*)d_in[13];
    const float* Wo2  = (const float*)d_in[14];
    const float* bo2  = (const float*)d_in[15];
    float* out = (float*)d_out;

    void *p_t1, *p_h, *p_pq, *p_wpq, *p_zero;
    cudaGetSymbolAddress(&p_t1,   g_t1);
    cudaGetSymbolAddress(&p_h,    g_h);
    cudaGetSymbolAddress(&p_pq,   g_pq);
    cudaGetSymbolAddress(&p_wpq,  g_Wpq);
    cudaGetSymbolAddress(&p_zero, g_zero);
    float* t1   = (float*)p_t1;
    float* h    = (float*)p_h;
    float* pq   = (float*)p_pq;
    float* wpq  = (float*)p_wpq;
    float* zero = (float*)p_zero;

    const int MB = (NN + 127) / 128;   // 157

    prep_kernel<<<128, 256>>>(Wm1, Wd2);

    // h = relu(x @ Win1^T + bin1) @ Win2^T + bin2
    sgemm_bias<<<dim3(1, MB), 256>>>(x,  Win1, bin1, t1, NN, IND, 64, 1);
    sgemm_bias<<<dim3(4, MB), 256>>>(t1, Win2, bin2, h,  NN, 64, HD, 0);

    // node projections: pq = h @ [Wa;Wb]^T
    sgemm_bias<<<dim3(2, MB), 256>>>(h, wpq, zero, pq, NN, HD, 128, 0);

    // edge messages -> Fs, Ft
    edge_fused_kernel<<<EE / 8, 256>>>(ei, bm1, Wm2, bm2);

    // sheaf diffusion layers (xb lives in g_h); xb-update fused into layer-1 H
    sheaf_H_kernel<<<NN / 4, 256>>>(Wd1, 0, 0);
    edge_scatter_kernel<<<EE / 4, 256>>>(ei);
    sheaf_H_kernel<<<NN / 4, 256>>>(Wd1, 1, 1);
    edge_scatter_kernel<<<EE / 4, 256>>>(ei);
    xb_update_kernel<<<NN * 64 / 256, 256>>>();

    // output MLP
    sgemm_bias<<<dim3(1, MB), 256>>>(h,  Wo1, bo1, t1,  NN, HD, 64, 1);
    sgemm_bias<<<dim3(1, MB), 256>>>(t1, Wo2, bo2, out, NN, 64, OD, 0);
}